// round 11
// baseline (speedup 1.0000x reference)
#include <cuda_runtime.h>
#include <cuda_fp16.h>
#include <math.h>
#include <float.h>
#include <cstdint>

#define TOKENS 16384
#define HIDDEN 4096
#define NEXP   256
#define TOPKG  4
#define TOPK   8

#define MT      64                 // tokens per CTA
#define NTHREADS 256               // 8 warps -> 2 per SMSP
#define KC      64                 // K floats per chunk
#define NCHUNK  (HIDDEN / KC)      // 64
#define RSTRIDE 144                // 128B data + 16B pad; conflict-free ldsm
#define AT      (MT * RSTRIDE)     // 9216  per A split tile
#define BT      (NEXP * RSTRIDE)   // 36864 per B split tile
#define BOFF    (2 * AT)           // 18432
#define STAGE_B (2 * AT + 2 * BT)  // 92160
#define GPITCH  264
#define SMEM_TOTAL (2 * STAGE_B)   // 184320 (>= gates 64*264*4 = 67584)

#define WSCALE   1024.0f
#define WUNSCALE 0.0009765625f

// pre-split weights: hi/lo fp16, [NEXP, HIDDEN] row-major (2 MB each)
__device__ __half g_wh[NEXP * HIDDEN];
__device__ __half g_wl[NEXP * HIDDEN];

__device__ __forceinline__ uint32_t smem_u32(const void* p) {
    uint32_t a;
    asm("{ .reg .u64 t; cvta.to.shared.u64 t, %1; cvt.u32.u64 %0, t; }" : "=r"(a) : "l"(p));
    return a;
}
__device__ __forceinline__ void ldsm4(uint32_t* r, uint32_t addr) {
    asm volatile("ldmatrix.sync.aligned.m8n8.x4.shared.b16 {%0,%1,%2,%3}, [%4];"
                 : "=r"(r[0]), "=r"(r[1]), "=r"(r[2]), "=r"(r[3]) : "r"(addr));
}
__device__ __forceinline__ void mma16816(float* d, const uint32_t* a, uint32_t b0, uint32_t b1) {
    asm volatile(
        "mma.sync.aligned.m16n8k16.row.col.f32.f16.f16.f32 "
        "{%0,%1,%2,%3}, {%4,%5,%6,%7}, {%8,%9}, {%0,%1,%2,%3};"
        : "+f"(d[0]), "+f"(d[1]), "+f"(d[2]), "+f"(d[3])
        : "r"(a[0]), "r"(a[1]), "r"(a[2]), "r"(a[3]), "r"(b0), "r"(b1));
}
__device__ __forceinline__ void cpasync16(uint32_t dst, const void* src) {
    asm volatile("cp.async.cg.shared.global [%0], [%1], 16;" :: "r"(dst), "l"(src));
}
#define CP_COMMIT() asm volatile("cp.async.commit_group;" ::: "memory")
#define CP_WAIT0()  asm volatile("cp.async.wait_group 0;" ::: "memory")

// split one float4 into 2 fp16x4 (hi + residual), store 8B to each tile
__device__ __forceinline__ void split_store2(char* t0, char* t1, uint32_t off,
                                             float4 v) {
    float f[4] = {v.x, v.y, v.z, v.w};
    __align__(8) __half h0[4], h1[4];
#pragma unroll
    for (int j = 0; j < 4; j++) {
        float a = f[j];
        __half b0 = __float2half_rn(a);
        float r1 = a - __half2float(b0);
        h0[j] = b0; h1[j] = __float2half_rn(r1);
    }
    *(uint2*)(t0 + off) = *(uint2*)h0;
    *(uint2*)(t1 + off) = *(uint2*)h1;
}

// ---------------------------------------------------------------------------
// w pre-split: fp32 -> (hi, lo) fp16 with 2^10 pre-scale (exact)
// ---------------------------------------------------------------------------
__global__ __launch_bounds__(256) void wsplit_kernel(const float* __restrict__ w)
{
    int idx = blockIdx.x * 256 + threadIdx.x;  // float4 index
    float4 v = ((const float4*)w)[idx];
    float f[4] = {v.x, v.y, v.z, v.w};
    __align__(8) __half h0[4], h1[4];
#pragma unroll
    for (int j = 0; j < 4; j++) {
        float a = f[j] * WSCALE;
        __half b0 = __float2half_rn(a);
        float r1 = a - __half2float(b0);
        h0[j] = b0; h1[j] = __float2half_rn(r1);
    }
    *(uint2*)&g_wh[idx * 4] = *(uint2*)h0;
    *(uint2*)&g_wl[idx * 4] = *(uint2*)h1;
}

// ---------------------------------------------------------------------------
// Fused MoE gate: 64 tokens x 256 experts per CTA, 256 threads (2 warps/SMSP),
// KC=64. fp16 2-term split, 3 HMMA passes; B via cp.async from pre-split gmem.
// ---------------------------------------------------------------------------
__global__ __launch_bounds__(NTHREADS, 1) void moe_gate_fused_kernel(
    const float* __restrict__ x,
    const float* __restrict__ bias, float* __restrict__ out)
{
    extern __shared__ char smem[];
    const uint32_t smem_base = smem_u32(smem);
    const int tid  = threadIdx.x;
    const int lane = tid & 31;
    const int wid  = tid >> 5;
    const int m0 = blockIdx.x * MT;

    const int wm = (wid & 1) * 32;   // warp m offset (2-way over 64)
    const int wn = (wid >> 1) * 64;  // warp n offset (4-way over 256)

    const uint32_t a_lane = (uint32_t)((lane & 15) * RSTRIDE + (lane >> 4) * 16);
    const uint32_t b_lane = (uint32_t)(((lane & 7) + ((lane >> 4) & 1) * 8) * RSTRIDE +
                                       ((lane >> 3) & 1) * 16);

    // A gmem mapping: row = tid>>2 (0..63), cq = tid&3 -> cols [cq*16, cq*16+16)
    const int r0 = tid >> 2;
    const int cq = tid & 3;
    const float* xp = x + (size_t)(m0 + r0) * HIDDEN + cq * 16;
    const uint32_t sts_off = (uint32_t)(r0 * RSTRIDE + cq * 32);

    // B cp.async mapping: thread t owns expert row t of BOTH hi and lo tiles
    const __half* whrow = g_wh + (size_t)tid * HIDDEN;
    const __half* wlrow = g_wl + (size_t)tid * HIDDEN;
    const uint32_t bh_off = (uint32_t)(BOFF + tid * RSTRIDE);
    const uint32_t bl_off = (uint32_t)(BOFF + BT + tid * RSTRIDE);

    float acc[2][8][4];
#pragma unroll
    for (int i = 0; i < 2; i++)
#pragma unroll
        for (int j = 0; j < 8; j++)
#pragma unroll
            for (int q = 0; q < 4; q++) acc[i][j][q] = 0.0f;

    float4 pa[4];

    // ---- prologue: chunk 0 -> stage 0 ----
    {
        uint32_t dh = smem_base + bh_off, dl = smem_base + bl_off;
#pragma unroll
        for (int j = 0; j < 8; j++) cpasync16(dh + j * 16, whrow + j * 8);
#pragma unroll
        for (int j = 0; j < 8; j++) cpasync16(dl + j * 16, wlrow + j * 8);
        CP_COMMIT();
    }
#pragma unroll
    for (int i = 0; i < 4; i++) pa[i] = *(const float4*)(xp + i * 4);
    {
        char* ab = smem;
#pragma unroll
        for (int i = 0; i < 4; i++)
            split_store2(ab, ab + AT, sts_off + i * 8, pa[i]);
    }
    CP_WAIT0();
    __syncthreads();

    // ---- main loop (double buffer; wait+sync at end of body) ----
#pragma unroll 1
    for (int k = 0; k < NCHUNK; k++) {
        const int kn = k + 1;
        if (kn < NCHUNK) {
            uint32_t st = smem_base + (uint32_t)(kn & 1) * STAGE_B;
            const __half* sh = whrow + kn * KC;
            const __half* sl = wlrow + kn * KC;
#pragma unroll
            for (int j = 0; j < 8; j++) cpasync16(st + bh_off + j * 16, sh + j * 8);
#pragma unroll
            for (int j = 0; j < 8; j++) cpasync16(st + bl_off + j * 16, sl + j * 8);
            CP_COMMIT();
            const float* xk = xp + kn * KC;
#pragma unroll
            for (int i = 0; i < 4; i++) pa[i] = *(const float4*)(xk + i * 4);
        }

        const uint32_t stage = smem_base + (uint32_t)(k & 1) * STAGE_B;
#pragma unroll
        for (int ks = 0; ks < 4; ks++) {
            const uint32_t ko = (uint32_t)(ks * 32);
            uint32_t fa[2][2][4];
#pragma unroll
            for (int s = 0; s < 2; s++) {
                const uint32_t abase = stage + s * AT + ko + a_lane;
                ldsm4(fa[s][0], abase + (uint32_t)(wm * RSTRIDE));
                ldsm4(fa[s][1], abase + (uint32_t)((wm + 16) * RSTRIDE));
            }
            uint32_t fb[4][4];
            // --- b0 fragments: passes a0*b0, a1*b0 ---
            {
                const uint32_t bbase = stage + BOFF + ko + b_lane;
#pragma unroll
                for (int jn = 0; jn < 4; jn++)
                    ldsm4(fb[jn], bbase + (uint32_t)((wn + jn * 16) * RSTRIDE));
            }
#pragma unroll
            for (int mt = 0; mt < 2; mt++)
#pragma unroll
                for (int j = 0; j < 8; j++)
                    mma16816(acc[mt][j], fa[0][mt],
                             fb[j >> 1][(j & 1) * 2], fb[j >> 1][(j & 1) * 2 + 1]);
#pragma unroll
            for (int mt = 0; mt < 2; mt++)
#pragma unroll
                for (int j = 0; j < 8; j++)
                    mma16816(acc[mt][j], fa[1][mt],
                             fb[j >> 1][(j & 1) * 2], fb[j >> 1][(j & 1) * 2 + 1]);
            // --- b1 fragments (reuse regs): pass a0*b1 ---
            {
                const uint32_t bbase = stage + BOFF + BT + ko + b_lane;
#pragma unroll
                for (int jn = 0; jn < 4; jn++)
                    ldsm4(fb[jn], bbase + (uint32_t)((wn + jn * 16) * RSTRIDE));
            }
#pragma unroll
            for (int mt = 0; mt < 2; mt++)
#pragma unroll
                for (int j = 0; j < 8; j++)
                    mma16816(acc[mt][j], fa[0][mt],
                             fb[j >> 1][(j & 1) * 2], fb[j >> 1][(j & 1) * 2 + 1]);
        }

        if (kn < NCHUNK) {
            char* ab = smem + (kn & 1) * STAGE_B;
#pragma unroll
            for (int i = 0; i < 4; i++)
                split_store2(ab, ab + AT, sts_off + i * 8, pa[i]);
        }
        CP_WAIT0();
        __syncthreads();
    }

    // ---- write gates to smem (undo the 2^10 w pre-scale) ----
    float* gsm = (float*)smem;
    {
        const int g = lane >> 2;
        const int tq = lane & 3;
#pragma unroll
        for (int mt = 0; mt < 2; mt++) {
#pragma unroll
            for (int j = 0; j < 8; j++) {
                int row = wm + mt * 16 + g;
                int col = wn + j * 8 + tq * 2;
                float2* p0 = (float2*)&gsm[row * GPITCH + col];
                float2* p1 = (float2*)&gsm[(row + 8) * GPITCH + col];
                *p0 = make_float2(acc[mt][j][0] * WUNSCALE, acc[mt][j][1] * WUNSCALE);
                *p1 = make_float2(acc[mt][j][2] * WUNSCALE, acc[mt][j][3] * WUNSCALE);
            }
        }
    }
    __syncthreads();

    // ---- routing: warp wid handles tokens wid*8 .. wid*8+7 (8*8 = 64) ----
    const unsigned FULL = 0xFFFFFFFFu;
#pragma unroll 1
    for (int tl = wid * 8; tl < wid * 8 + 8; tl++) {
        const int t = m0 + tl;
        float orig[8], v[8];
        float m1 = -FLT_MAX, m2 = -FLT_MAX;
#pragma unroll
        for (int j = 0; j < 8; j++) {
            int e = lane * 8 + j;
            float gv = gsm[tl * GPITCH + e];
            float s;
            if (gv >= 0.0f) { s = 1.0f / (1.0f + expf(-gv)); }
            else { float eg = expf(gv); s = eg / (1.0f + eg); }
            orig[j] = s;
            float sc2 = s + __ldg(&bias[e]);
            v[j] = sc2;
            if (sc2 > m1) { m2 = m1; m1 = sc2; }
            else if (sc2 > m2) { m2 = sc2; }
        }

#pragma unroll
        for (int off = 1; off <= 2; off <<= 1) {
            float o1 = __shfl_xor_sync(FULL, m1, off);
            float o2 = __shfl_xor_sync(FULL, m2, off);
            if (o1 > m1) { m2 = fmaxf(m1, o2); m1 = o1; }
            else         { m2 = fmaxf(m2, o1); }
        }
        float gs = m1 + m2;

        float gsg = __shfl_sync(FULL, gs, (lane & 7) * 4);

        int gidx = lane & 7;
        int rank = 0;
#pragma unroll
        for (int h = 0; h < 8; h++) {
            float other = __shfl_sync(FULL, gsg, h);
            rank += (other < gsg || (other == gsg && h < gidx)) ? 1 : 0;
        }
        unsigned keepmask = __ballot_sync(FULL, (lane < 8) && (rank < TOPKG));
        bool kept = (keepmask >> (lane >> 2)) & 1u;

#pragma unroll
        for (int j = 0; j < 8; j++) v[j] = kept ? v[j] : 0.0f;

        int selIdx[8]; float selOrig[8]; float ssum = 0.0f;
#pragma unroll
        for (int k = 0; k < TOPK; k++) {
            float bv = FLT_MAX; int bi = 0x7FFFFFFF; float bo = 0.0f;
#pragma unroll
            for (int j = 0; j < 8; j++) {
                int e = lane * 8 + j;
                if (v[j] < bv || (v[j] == bv && e < bi)) { bv = v[j]; bi = e; bo = orig[j]; }
            }
#pragma unroll
            for (int off = 16; off > 0; off >>= 1) {
                float ov = __shfl_xor_sync(FULL, bv, off);
                int   oi = __shfl_xor_sync(FULL, bi, off);
                float oo = __shfl_xor_sync(FULL, bo, off);
                if (ov < bv || (ov == bv && oi < bi)) { bv = ov; bi = oi; bo = oo; }
            }
            selIdx[k] = bi; selOrig[k] = bo; ssum += bo;
            if ((bi >> 3) == lane) v[bi & 7] = FLT_MAX;
        }

        float inv = 2.5f / (ssum + 1e-20f);
        if (lane < 8) {
            out[(size_t)t * TOPK + lane] = (float)selIdx[lane];
            out[(size_t)TOKENS * TOPK + (size_t)t * TOPK + lane] = selOrig[lane] * inv;
        }
    }
}

extern "C" void kernel_launch(void* const* d_in, const int* in_sizes, int n_in,
                              void* d_out, int out_size)
{
    const float* x    = (const float*)d_in[0];
    const float* w    = (const float*)d_in[1];
    const float* bias = (const float*)d_in[2];
    float* out = (float*)d_out;

    cudaFuncSetAttribute(moe_gate_fused_kernel,
                         cudaFuncAttributeMaxDynamicSharedMemorySize, SMEM_TOTAL);

    wsplit_kernel<<<NEXP * HIDDEN / 4 / 256, 256>>>(w);
    moe_gate_fused_kernel<<<TOKENS / MT, NTHREADS, SMEM_TOTAL>>>(x, bias, out);
}

// round 12
// speedup vs baseline: 1.3170x; 1.3170x over previous
#include <cuda_runtime.h>
#include <cuda_fp16.h>
#include <math.h>
#include <float.h>
#include <cstdint>

#define TOKENS 16384
#define HIDDEN 4096
#define NEXP   256
#define TOPKG  4
#define TOPK   8

#define MT      128                // tokens per CTA
#define NTHREADS 256               // 8 warps, warp tile m64 x n64
#define KC      32
#define NCHUNK  (HIDDEN / KC)      // 128
#define RSTRIDE 80                 // 64B data + 16B pad -> conflict-free ldsm
#define AT      (MT * RSTRIDE)     // 10240 per A split tile
#define BT      (NEXP * RSTRIDE)   // 20480 per B split tile
#define BOFF    (2 * AT)           // 20480
#define STAGE_B (2 * AT + 2 * BT)  // 61440
#define GPITCH  264
#define SMEM_TOTAL (MT * GPITCH * 4)   // 135168 >= 2*STAGE_B (122880)

#define WSCALE   1024.0f
#define WUNSCALE 0.0009765625f

// pre-split weights: hi/lo fp16, [NEXP, HIDDEN] row-major (2 MB each)
__device__ __half g_wh[NEXP * HIDDEN];
__device__ __half g_wl[NEXP * HIDDEN];

__device__ __forceinline__ uint32_t smem_u32(const void* p) {
    uint32_t a;
    asm("{ .reg .u64 t; cvta.to.shared.u64 t, %1; cvt.u32.u64 %0, t; }" : "=r"(a) : "l"(p));
    return a;
}
__device__ __forceinline__ void ldsm4(uint32_t* r, uint32_t addr) {
    asm volatile("ldmatrix.sync.aligned.m8n8.x4.shared.b16 {%0,%1,%2,%3}, [%4];"
                 : "=r"(r[0]), "=r"(r[1]), "=r"(r[2]), "=r"(r[3]) : "r"(addr));
}
__device__ __forceinline__ void mma16816(float* d, const uint32_t* a, uint32_t b0, uint32_t b1) {
    asm volatile(
        "mma.sync.aligned.m16n8k16.row.col.f32.f16.f16.f32 "
        "{%0,%1,%2,%3}, {%4,%5,%6,%7}, {%8,%9}, {%0,%1,%2,%3};"
        : "+f"(d[0]), "+f"(d[1]), "+f"(d[2]), "+f"(d[3])
        : "r"(a[0]), "r"(a[1]), "r"(a[2]), "r"(a[3]), "r"(b0), "r"(b1));
}
__device__ __forceinline__ void cpasync16(uint32_t dst, const void* src) {
    asm volatile("cp.async.cg.shared.global [%0], [%1], 16;" :: "r"(dst), "l"(src));
}
#define CP_COMMIT() asm volatile("cp.async.commit_group;" ::: "memory")
#define CP_WAIT0()  asm volatile("cp.async.wait_group 0;" ::: "memory")

// split one float4 into 2 fp16x4 (hi + residual), store 8B to each tile
__device__ __forceinline__ void split_store2(char* t0, char* t1, uint32_t off,
                                             float4 v) {
    float f[4] = {v.x, v.y, v.z, v.w};
    __align__(8) __half h0[4], h1[4];
#pragma unroll
    for (int j = 0; j < 4; j++) {
        float a = f[j];
        __half b0 = __float2half_rn(a);
        float r1 = a - __half2float(b0);
        h0[j] = b0; h1[j] = __float2half_rn(r1);
    }
    *(uint2*)(t0 + off) = *(uint2*)h0;
    *(uint2*)(t1 + off) = *(uint2*)h1;
}

// ---------------------------------------------------------------------------
// w pre-split: fp32 -> (hi, lo) fp16 with 2^10 pre-scale (exact)
// ---------------------------------------------------------------------------
__global__ __launch_bounds__(256) void wsplit_kernel(const float* __restrict__ w)
{
    int idx = blockIdx.x * 256 + threadIdx.x;  // float4 index
    float4 v = ((const float4*)w)[idx];
    float f[4] = {v.x, v.y, v.z, v.w};
    __align__(8) __half h0[4], h1[4];
#pragma unroll
    for (int j = 0; j < 4; j++) {
        float a = f[j] * WSCALE;
        __half b0 = __float2half_rn(a);
        float r1 = a - __half2float(b0);
        h0[j] = b0; h1[j] = __float2half_rn(r1);
    }
    *(uint2*)&g_wh[idx * 4] = *(uint2*)h0;
    *(uint2*)&g_wl[idx * 4] = *(uint2*)h1;
}

// ---------------------------------------------------------------------------
// Fused MoE gate: 128 tokens x 256 experts per CTA, 256 threads,
// warp tile m64 x n64, fp16 2-term split, 3 HMMA passes.
// ---------------------------------------------------------------------------
__global__ __launch_bounds__(NTHREADS, 1) void moe_gate_fused_kernel(
    const float* __restrict__ x,
    const float* __restrict__ bias, float* __restrict__ out)
{
    extern __shared__ char smem[];
    const uint32_t smem_base = smem_u32(smem);
    const int tid  = threadIdx.x;
    const int lane = tid & 31;
    const int wid  = tid >> 5;
    const int m0 = blockIdx.x * MT;

    const int wm = (wid & 1) * 64;   // warp m offset (2-way over 128)
    const int wn = (wid >> 1) * 64;  // warp n offset (4-way over 256)

    const uint32_t a_lane = (uint32_t)((lane & 15) * RSTRIDE + (lane >> 4) * 16);
    const uint32_t b_lane = (uint32_t)(((lane & 7) + ((lane >> 4) & 1) * 8) * RSTRIDE +
                                       ((lane >> 3) & 1) * 16);

    // A gmem mapping: row = tid>>1 (0..127), cq = tid&1 -> cols [cq*16, cq*16+16)
    const int r0 = tid >> 1;
    const int cq = tid & 1;
    const float* xp = x + (size_t)(m0 + r0) * HIDDEN + cq * 16;
    const uint32_t sts_off = (uint32_t)(r0 * RSTRIDE + cq * 32);

    // B cp.async mapping: pair ids tid (s=0,row=tid) and tid+256 (s=1,row=tid)
    // each pair copies 4 x 16B (64B = one chunk-row)
    const __half* wrow_h = g_wh + (size_t)tid * HIDDEN;
    const __half* wrow_l = g_wl + (size_t)tid * HIDDEN;
    const uint32_t bh_off = (uint32_t)(BOFF + tid * RSTRIDE);
    const uint32_t bl_off = (uint32_t)(BOFF + BT + tid * RSTRIDE);

    float acc[4][8][4];
#pragma unroll
    for (int i = 0; i < 4; i++)
#pragma unroll
        for (int j = 0; j < 8; j++)
#pragma unroll
            for (int q = 0; q < 4; q++) acc[i][j][q] = 0.0f;

    float4 pa[4];

    // ---- prologue: chunk 0 -> stage 0 ----
    {
        uint32_t dh = smem_base + bh_off, dl = smem_base + bl_off;
#pragma unroll
        for (int j = 0; j < 4; j++) cpasync16(dh + j * 16, wrow_h + j * 8);
#pragma unroll
        for (int j = 0; j < 4; j++) cpasync16(dl + j * 16, wrow_l + j * 8);
        CP_COMMIT();
    }
#pragma unroll
    for (int i = 0; i < 4; i++) pa[i] = *(const float4*)(xp + i * 4);
    {
        char* ab = smem;
#pragma unroll
        for (int i = 0; i < 4; i++)
            split_store2(ab, ab + AT, sts_off + i * 8, pa[i]);
    }
    CP_WAIT0();
    __syncthreads();

    // ---- main loop (double buffer; R6-proven ordering) ----
#pragma unroll 1
    for (int k = 0; k < NCHUNK; k++) {
        const int kn = k + 1;
        if (kn < NCHUNK) {
            uint32_t st = smem_base + (uint32_t)(kn & 1) * STAGE_B;
            const __half* sh = wrow_h + kn * KC;
            const __half* sl = wrow_l + kn * KC;
#pragma unroll
            for (int j = 0; j < 4; j++) cpasync16(st + bh_off + j * 16, sh + j * 8);
#pragma unroll
            for (int j = 0; j < 4; j++) cpasync16(st + bl_off + j * 16, sl + j * 8);
            CP_COMMIT();
            const float* xk = xp + kn * KC;
#pragma unroll
            for (int i = 0; i < 4; i++) pa[i] = *(const float4*)(xk + i * 4);
        }

        const uint32_t stage = smem_base + (uint32_t)(k & 1) * STAGE_B;
#pragma unroll
        for (int ks = 0; ks < 2; ks++) {
            const uint32_t ko = (uint32_t)(ks * 32);
            // A fragments: 2 splits x 4 m-tiles (m64)
            uint32_t fa[2][4][4];
#pragma unroll
            for (int s = 0; s < 2; s++) {
                const uint32_t abase = stage + s * AT + ko + a_lane;
#pragma unroll
                for (int mt = 0; mt < 4; mt++)
                    ldsm4(fa[s][mt], abase + (uint32_t)((wm + mt * 16) * RSTRIDE));
            }
            uint32_t fb[4][4];
            // --- b0 fragments: passes a0*b0, a1*b0 ---
            {
                const uint32_t bbase = stage + BOFF + ko + b_lane;
#pragma unroll
                for (int jn = 0; jn < 4; jn++)
                    ldsm4(fb[jn], bbase + (uint32_t)((wn + jn * 16) * RSTRIDE));
            }
#pragma unroll
            for (int mt = 0; mt < 4; mt++)
#pragma unroll
                for (int j = 0; j < 8; j++)
                    mma16816(acc[mt][j], fa[0][mt],
                             fb[j >> 1][(j & 1) * 2], fb[j >> 1][(j & 1) * 2 + 1]);
#pragma unroll
            for (int mt = 0; mt < 4; mt++)
#pragma unroll
                for (int j = 0; j < 8; j++)
                    mma16816(acc[mt][j], fa[1][mt],
                             fb[j >> 1][(j & 1) * 2], fb[j >> 1][(j & 1) * 2 + 1]);
            // --- b1 fragments (reuse regs): pass a0*b1 ---
            {
                const uint32_t bbase = stage + BOFF + BT + ko + b_lane;
#pragma unroll
                for (int jn = 0; jn < 4; jn++)
                    ldsm4(fb[jn], bbase + (uint32_t)((wn + jn * 16) * RSTRIDE));
            }
#pragma unroll
            for (int mt = 0; mt < 4; mt++)
#pragma unroll
                for (int j = 0; j < 8; j++)
                    mma16816(acc[mt][j], fa[0][mt],
                             fb[j >> 1][(j & 1) * 2], fb[j >> 1][(j & 1) * 2 + 1]);
        }

        if (kn < NCHUNK) {
            char* ab = smem + (kn & 1) * STAGE_B;
#pragma unroll
            for (int i = 0; i < 4; i++)
                split_store2(ab, ab + AT, sts_off + i * 8, pa[i]);
        }
        CP_WAIT0();
        __syncthreads();
    }

    // ---- write gates to smem (undo the 2^10 w pre-scale) ----
    float* gsm = (float*)smem;
    {
        const int g = lane >> 2;
        const int tq = lane & 3;
#pragma unroll
        for (int mt = 0; mt < 4; mt++) {
#pragma unroll
            for (int j = 0; j < 8; j++) {
                int row = wm + mt * 16 + g;
                int col = wn + j * 8 + tq * 2;
                float2* p0 = (float2*)&gsm[row * GPITCH + col];
                float2* p1 = (float2*)&gsm[(row + 8) * GPITCH + col];
                *p0 = make_float2(acc[mt][j][0] * WUNSCALE, acc[mt][j][1] * WUNSCALE);
                *p1 = make_float2(acc[mt][j][2] * WUNSCALE, acc[mt][j][3] * WUNSCALE);
            }
        }
    }
    __syncthreads();

    // ---- routing: warp wid handles tokens wid*16 .. wid*16+15 ----
    const unsigned FULL = 0xFFFFFFFFu;
#pragma unroll 1
    for (int tl = wid * 16; tl < wid * 16 + 16; tl++) {
        const int t = m0 + tl;
        float orig[8], v[8];
        float m1 = -FLT_MAX, m2 = -FLT_MAX;
#pragma unroll
        for (int j = 0; j < 8; j++) {
            int e = lane * 8 + j;
            float gv = gsm[tl * GPITCH + e];
            float s;
            if (gv >= 0.0f) { s = 1.0f / (1.0f + expf(-gv)); }
            else { float eg = expf(gv); s = eg / (1.0f + eg); }
            orig[j] = s;
            float sc2 = s + __ldg(&bias[e]);
            v[j] = sc2;
            if (sc2 > m1) { m2 = m1; m1 = sc2; }
            else if (sc2 > m2) { m2 = sc2; }
        }

#pragma unroll
        for (int off = 1; off <= 2; off <<= 1) {
            float o1 = __shfl_xor_sync(FULL, m1, off);
            float o2 = __shfl_xor_sync(FULL, m2, off);
            if (o1 > m1) { m2 = fmaxf(m1, o2); m1 = o1; }
            else         { m2 = fmaxf(m2, o1); }
        }
        float gs = m1 + m2;

        float gsg = __shfl_sync(FULL, gs, (lane & 7) * 4);

        int gidx = lane & 7;
        int rank = 0;
#pragma unroll
        for (int h = 0; h < 8; h++) {
            float other = __shfl_sync(FULL, gsg, h);
            rank += (other < gsg || (other == gsg && h < gidx)) ? 1 : 0;
        }
        unsigned keepmask = __ballot_sync(FULL, (lane < 8) && (rank < TOPKG));
        bool kept = (keepmask >> (lane >> 2)) & 1u;

#pragma unroll
        for (int j = 0; j < 8; j++) v[j] = kept ? v[j] : 0.0f;

        int selIdx[8]; float selOrig[8]; float ssum = 0.0f;
#pragma unroll
        for (int k = 0; k < TOPK; k++) {
            float bv = FLT_MAX; int bi = 0x7FFFFFFF; float bo = 0.0f;
#pragma unroll
            for (int j = 0; j < 8; j++) {
                int e = lane * 8 + j;
                if (v[j] < bv || (v[j] == bv && e < bi)) { bv = v[j]; bi = e; bo = orig[j]; }
            }
#pragma unroll
            for (int off = 16; off > 0; off >>= 1) {
                float ov = __shfl_xor_sync(FULL, bv, off);
                int   oi = __shfl_xor_sync(FULL, bi, off);
                float oo = __shfl_xor_sync(FULL, bo, off);
                if (ov < bv || (ov == bv && oi < bi)) { bv = ov; bi = oi; bo = oo; }
            }
            selIdx[k] = bi; selOrig[k] = bo; ssum += bo;
            if ((bi >> 3) == lane) v[bi & 7] = FLT_MAX;
        }

        float inv = 2.5f / (ssum + 1e-20f);
        if (lane < 8) {
            out[(size_t)t * TOPK + lane] = (float)selIdx[lane];
            out[(size_t)TOKENS * TOPK + (size_t)t * TOPK + lane] = selOrig[lane] * inv;
        }
    }
}

extern "C" void kernel_launch(void* const* d_in, const int* in_sizes, int n_in,
                              void* d_out, int out_size)
{
    const float* x    = (const float*)d_in[0];
    const float* w    = (const float*)d_in[1];
    const float* bias = (const float*)d_in[2];
    float* out = (float*)d_out;

    cudaFuncSetAttribute(moe_gate_fused_kernel,
                         cudaFuncAttributeMaxDynamicSharedMemorySize, SMEM_TOTAL);

    wsplit_kernel<<<NEXP * HIDDEN / 4 / 256, 256>>>(w);
    moe_gate_fused_kernel<<<TOKENS / MT, NTHREADS, SMEM_TOTAL>>>(x, bias, out);
}

// round 13
// speedup vs baseline: 1.6311x; 1.2385x over previous
#include <cuda_runtime.h>
#include <cuda_fp16.h>
#include <math.h>
#include <float.h>
#include <cstdint>

#define TOKENS 16384
#define HIDDEN 4096
#define NEXP   256
#define TOPKG  4
#define TOPK   8

#define MT      128                // tokens per CTA
#define NTHREADS 512
#define KC      32
#define NCHUNK  (HIDDEN / KC)      // 128
#define RSTRIDE 80                 // 64B data + 16B pad -> conflict-free ldsm
#define AT      (MT * RSTRIDE)     // 10240 per A split tile
#define BT      (NEXP * RSTRIDE)   // 20480 per B split tile
#define BOFF    (2 * AT)           // 20480
#define STAGE_B (2 * AT + 2 * BT)  // 61440
#define GPITCH  264
#define SMEM_TOTAL (MT * GPITCH * 4)  // 135168 >= 2*STAGE_B (122880)

#define WSCALE   1024.0f
#define WUNSCALE 0.0009765625f

// named split barriers: W1/W2 = stage0/1 written; 3/4 = stage0/1 readers done
#define BAR_SYNC(id)   asm volatile("bar.sync %0, 1024;"   :: "r"(id) : "memory")
#define BAR_ARRIVE(id) asm volatile("bar.arrive %0, 1024;" :: "r"(id) : "memory")

__device__ __forceinline__ uint32_t smem_u32(const void* p) {
    uint32_t a;
    asm("{ .reg .u64 t; cvta.to.shared.u64 t, %1; cvt.u32.u64 %0, t; }" : "=r"(a) : "l"(p));
    return a;
}
__device__ __forceinline__ void ldsm4(uint32_t* r, uint32_t addr) {
    asm volatile("ldmatrix.sync.aligned.m8n8.x4.shared.b16 {%0,%1,%2,%3}, [%4];"
                 : "=r"(r[0]), "=r"(r[1]), "=r"(r[2]), "=r"(r[3]) : "r"(addr));
}
__device__ __forceinline__ void mma16816(float* d, const uint32_t* a, uint32_t b0, uint32_t b1) {
    asm volatile(
        "mma.sync.aligned.m16n8k16.row.col.f32.f16.f16.f32 "
        "{%0,%1,%2,%3}, {%4,%5,%6,%7}, {%8,%9}, {%0,%1,%2,%3};"
        : "+f"(d[0]), "+f"(d[1]), "+f"(d[2]), "+f"(d[3])
        : "r"(a[0]), "r"(a[1]), "r"(a[2]), "r"(a[3]), "r"(b0), "r"(b1));
}

// split one float4 into 2 fp16x4 (hi + residual) and store 8B to each tile
__device__ __forceinline__ void split_store2(char* t0, char* t1, uint32_t off,
                                             float4 v, float scale) {
    float f[4] = {v.x, v.y, v.z, v.w};
    __align__(8) __half h0[4], h1[4];
#pragma unroll
    for (int j = 0; j < 4; j++) {
        float a = f[j] * scale;
        __half b0 = __float2half_rn(a);
        float r1 = a - __half2float(b0);
        h0[j] = b0; h1[j] = __float2half_rn(r1);
    }
    *(uint2*)(t0 + off) = *(uint2*)h0;
    *(uint2*)(t1 + off) = *(uint2*)h1;
}

// ---------------------------------------------------------------------------
// Fused MoE gate: GEMM (128 tokens x 256 experts per CTA, fp16 2-term split,
// 3 HMMA passes) + routing. R6 structure; per-chunk __syncthreads replaced by
// split arrive/wait named barriers so warps drift out of lockstep.
// ---------------------------------------------------------------------------
__global__ __launch_bounds__(NTHREADS, 1) void moe_gate_fused_kernel(
    const float* __restrict__ x, const float* __restrict__ w,
    const float* __restrict__ bias, float* __restrict__ out)
{
    extern __shared__ char smem[];
    const uint32_t smem_base = smem_u32(smem);
    const int tid  = threadIdx.x;
    const int lane = tid & 31;
    const int wid  = tid >> 5;
    const int m0 = blockIdx.x * MT;

    const int wm = (wid & 3) * 32;   // warp m offset (4-way over 128)
    const int wn = (wid >> 2) * 64;  // warp n offset (4-way over 256)

    const uint32_t a_lane = (uint32_t)((lane & 15) * RSTRIDE + (lane >> 4) * 16);
    const uint32_t b_lane = (uint32_t)(((lane & 7) + ((lane >> 4) & 1) * 8) * RSTRIDE +
                                       ((lane >> 3) & 1) * 16);

    // gmem mapping: idx = tid + 512*i ; row = idx>>3, c4 = idx&7
    const int r0 = tid >> 3;          // 0..63
    const int c4 = tid & 7;
    const float* xp = x + (size_t)(m0 + r0) * HIDDEN + c4 * 4;
    const float* wp = w + (size_t)r0 * HIDDEN + c4 * 4;
    const uint32_t sts_off = (uint32_t)(r0 * RSTRIDE + c4 * 8);

    float acc[2][8][4];
#pragma unroll
    for (int i = 0; i < 2; i++)
#pragma unroll
        for (int j = 0; j < 8; j++)
#pragma unroll
            for (int q = 0; q < 4; q++) acc[i][j][q] = 0.0f;

    float4 pa[2], pb[4];

    // ---- prologue: chunk 0 -> stage 0 ----
#pragma unroll
    for (int i = 0; i < 2; i++) pa[i] = *(const float4*)(xp + (size_t)i * 64 * HIDDEN);
#pragma unroll
    for (int i = 0; i < 4; i++) pb[i] = *(const float4*)(wp + (size_t)i * 64 * HIDDEN);
    {
        char* ab = smem;            char* bb = smem + BOFF;
#pragma unroll
        for (int i = 0; i < 2; i++)
            split_store2(ab, ab + AT, sts_off + i * 64 * RSTRIDE, pa[i], 1.0f);
#pragma unroll
        for (int i = 0; i < 4; i++)
            split_store2(bb, bb + BT, sts_off + i * 64 * RSTRIDE, pb[i], WSCALE);
    }
    __syncthreads();
    // prime the split barriers: stage0 is written (W0 -> id 1); stage1 is free (R1 -> id 4)
    BAR_ARRIVE(1);
    BAR_ARRIVE(4);

    // ---- main loop (split-barrier pipeline) ----
#pragma unroll 1
    for (int k = 0; k < NCHUNK; k++) {
        const int kn = k + 1;
        const int p = k & 1;
        const int q = kn & 1;

        if (kn < NCHUNK) {
            BAR_SYNC(3 + q);   // stage q readers (chunk k-1) done -> safe to refill
            const float* xk = xp + kn * KC;
            const float* wk = wp + kn * KC;
#pragma unroll
            for (int i = 0; i < 2; i++) pa[i] = *(const float4*)(xk + (size_t)i * 64 * HIDDEN);
#pragma unroll
            for (int i = 0; i < 4; i++) pb[i] = *(const float4*)(wk + (size_t)i * 64 * HIDDEN);
        }

        BAR_SYNC(1 + p);       // stage p fully written (arrivals from chunk k-1)

        const uint32_t stage = smem_base + (uint32_t)p * STAGE_B;
#pragma unroll
        for (int ks = 0; ks < 2; ks++) {
            const uint32_t ko = (uint32_t)(ks * 32);
            uint32_t fa[2][2][4];
#pragma unroll
            for (int s = 0; s < 2; s++) {
                const uint32_t abase = stage + s * AT + ko + a_lane;
                ldsm4(fa[s][0], abase + (uint32_t)(wm * RSTRIDE));
                ldsm4(fa[s][1], abase + (uint32_t)((wm + 16) * RSTRIDE));
            }
            uint32_t fb[2][4][4];
#pragma unroll
            for (int s = 0; s < 2; s++) {
                const uint32_t bbase = stage + BOFF + s * BT + ko + b_lane;
#pragma unroll
                for (int jn = 0; jn < 4; jn++)
                    ldsm4(fb[s][jn], bbase + (uint32_t)((wn + jn * 16) * RSTRIDE));
            }
            // passes: a0*b0, a0*b1, a1*b0
#pragma unroll
            for (int mt = 0; mt < 2; mt++)
#pragma unroll
                for (int j = 0; j < 8; j++)
                    mma16816(acc[mt][j], fa[0][mt],
                             fb[0][j >> 1][(j & 1) * 2], fb[0][j >> 1][(j & 1) * 2 + 1]);
#pragma unroll
            for (int mt = 0; mt < 2; mt++)
#pragma unroll
                for (int j = 0; j < 8; j++)
                    mma16816(acc[mt][j], fa[0][mt],
                             fb[1][j >> 1][(j & 1) * 2], fb[1][j >> 1][(j & 1) * 2 + 1]);
#pragma unroll
            for (int mt = 0; mt < 2; mt++)
#pragma unroll
                for (int j = 0; j < 8; j++)
                    mma16816(acc[mt][j], fa[1][mt],
                             fb[0][j >> 1][(j & 1) * 2], fb[0][j >> 1][(j & 1) * 2 + 1]);
        }

        BAR_ARRIVE(3 + p);     // done reading stage p (non-blocking)

        if (kn < NCHUNK) {
            char* base = smem + q * STAGE_B;
            char* ab = base;        char* bb = base + BOFF;
#pragma unroll
            for (int i = 0; i < 2; i++)
                split_store2(ab, ab + AT, sts_off + i * 64 * RSTRIDE, pa[i], 1.0f);
#pragma unroll
            for (int i = 0; i < 4; i++)
                split_store2(bb, bb + BT, sts_off + i * 64 * RSTRIDE, pb[i], WSCALE);
            BAR_ARRIVE(1 + q); // stage q written (non-blocking)
        }
    }

    __syncthreads();  // all MMA done before gates overlay reuses smem

    // ---- write gates to smem (undo the 2^10 w pre-scale) ----
    float* gsm = (float*)smem;
    {
        const int g = lane >> 2;
        const int tq = lane & 3;
#pragma unroll
        for (int mt = 0; mt < 2; mt++) {
#pragma unroll
            for (int j = 0; j < 8; j++) {
                int row = wm + mt * 16 + g;
                int col = wn + j * 8 + tq * 2;
                float2* p0 = (float2*)&gsm[row * GPITCH + col];
                float2* p1 = (float2*)&gsm[(row + 8) * GPITCH + col];
                *p0 = make_float2(acc[mt][j][0] * WUNSCALE, acc[mt][j][1] * WUNSCALE);
                *p1 = make_float2(acc[mt][j][2] * WUNSCALE, acc[mt][j][3] * WUNSCALE);
            }
        }
    }
    __syncthreads();

    // ---- routing: warp wid handles tokens wid*8 .. wid*8+7 (16*8 = 128) ----
    const unsigned FULL = 0xFFFFFFFFu;
#pragma unroll 1
    for (int tl = wid * 8; tl < wid * 8 + 8; tl++) {
        const int t = m0 + tl;
        float orig[8], v[8];
        float m1 = -FLT_MAX, m2 = -FLT_MAX;
#pragma unroll
        for (int j = 0; j < 8; j++) {
            int e = lane * 8 + j;
            float gv = gsm[tl * GPITCH + e];
            float s;
            if (gv >= 0.0f) { s = 1.0f / (1.0f + expf(-gv)); }
            else { float eg = expf(gv); s = eg / (1.0f + eg); }
            orig[j] = s;
            float sc2 = s + __ldg(&bias[e]);
            v[j] = sc2;
            if (sc2 > m1) { m2 = m1; m1 = sc2; }
            else if (sc2 > m2) { m2 = sc2; }
        }

#pragma unroll
        for (int off = 1; off <= 2; off <<= 1) {
            float o1 = __shfl_xor_sync(FULL, m1, off);
            float o2 = __shfl_xor_sync(FULL, m2, off);
            if (o1 > m1) { m2 = fmaxf(m1, o2); m1 = o1; }
            else         { m2 = fmaxf(m2, o1); }
        }
        float gs = m1 + m2;

        float gsg = __shfl_sync(FULL, gs, (lane & 7) * 4);

        int gidx = lane & 7;
        int rank = 0;
#pragma unroll
        for (int h = 0; h < 8; h++) {
            float other = __shfl_sync(FULL, gsg, h);
            rank += (other < gsg || (other == gsg && h < gidx)) ? 1 : 0;
        }
        unsigned keepmask = __ballot_sync(FULL, (lane < 8) && (rank < TOPKG));
        bool kept = (keepmask >> (lane >> 2)) & 1u;

#pragma unroll
        for (int j = 0; j < 8; j++) v[j] = kept ? v[j] : 0.0f;

        int selIdx[8]; float selOrig[8]; float ssum = 0.0f;
#pragma unroll
        for (int k = 0; k < TOPK; k++) {
            float bv = FLT_MAX; int bi = 0x7FFFFFFF; float bo = 0.0f;
#pragma unroll
            for (int j = 0; j < 8; j++) {
                int e = lane * 8 + j;
                if (v[j] < bv || (v[j] == bv && e < bi)) { bv = v[j]; bi = e; bo = orig[j]; }
            }
#pragma unroll
            for (int off = 16; off > 0; off >>= 1) {
                float ov = __shfl_xor_sync(FULL, bv, off);
                int   oi = __shfl_xor_sync(FULL, bi, off);
                float oo = __shfl_xor_sync(FULL, bo, off);
                if (ov < bv || (ov == bv && oi < bi)) { bv = ov; bi = oi; bo = oo; }
            }
            selIdx[k] = bi; selOrig[k] = bo; ssum += bo;
            if ((bi >> 3) == lane) v[bi & 7] = FLT_MAX;
        }

        float inv = 2.5f / (ssum + 1e-20f);
        if (lane < 8) {
            out[(size_t)t * TOPK + lane] = (float)selIdx[lane];
            out[(size_t)TOKENS * TOPK + (size_t)t * TOPK + lane] = selOrig[lane] * inv;
        }
    }
}

extern "C" void kernel_launch(void* const* d_in, const int* in_sizes, int n_in,
                              void* d_out, int out_size)
{
    const float* x    = (const float*)d_in[0];
    const float* w    = (const float*)d_in[1];
    const float* bias = (const float*)d_in[2];
    float* out = (float*)d_out;

    cudaFuncSetAttribute(moe_gate_fused_kernel,
                         cudaFuncAttributeMaxDynamicSharedMemorySize, SMEM_TOTAL);
    moe_gate_fused_kernel<<<TOKENS / MT, NTHREADS, SMEM_TOTAL>>>(x, w, bias, out);
}